// round 3
// baseline (speedup 1.0000x reference)
#include <cuda_runtime.h>
#include <math.h>

#define BATCH 32
#define CH    128
#define SEQ   1024
#define RINN  256
#define RHH   512
#define OCC   128
#define MTOT  (BATCH*SEQ)   // 32768

// ---------------- device scratch (no allocations allowed) ----------------
__device__ float g_scale[CH];
__device__ float g_shift[CH];
__device__ float g_winf[RINN*CH];
__device__ float g_binf[RINN];
__device__ float g_inp[MTOT*RINN];            // (B*L, 256)
__device__ float g_xgate[MTOT*RHH];           // (B*L, 512)
__device__ float g_outs[MTOT*RHH];            // (B*L, 512)
__device__ float g_h[2][BATCH*RHH];           // double-buffered hidden state
__device__ unsigned int g_bar[4];             // per-batch-group barrier counters

// ---------------- BN statistics -> scale/shift --------------------------
__global__ void bn_stats_k(const float* __restrict__ x,
                           const float* __restrict__ gamma,
                           const float* __restrict__ beta) {
    int c = blockIdx.x;
    int tid = threadIdx.x;
    float s = 0.f, s2 = 0.f;
    for (int i = tid; i < BATCH*SEQ; i += 256) {
        int b = i >> 10, p = i & 1023;
        float v = x[(((b*CH + c) << 10) + p)];
        s += v; s2 += v*v;
    }
    __shared__ float sh0[256], sh1[256];
    sh0[tid] = s; sh1[tid] = s2;
    __syncthreads();
    for (int o = 128; o > 0; o >>= 1) {
        if (tid < o) { sh0[tid] += sh0[tid+o]; sh1[tid] += sh1[tid+o]; }
        __syncthreads();
    }
    if (tid == 0) {
        const float inv = 1.0f / (float)(BATCH*SEQ);
        float mean = sh0[0] * inv;
        float var  = sh1[0] * inv - mean*mean;
        float sc = gamma[c] * rsqrtf(var + 1e-5f);
        g_scale[c] = sc;
        g_shift[c] = beta[c] - mean * sc;
    }
}

// ------------- fold BN into w_in / b_in, reset barriers ------------------
__global__ void fold_k(const float* __restrict__ w_in,
                       const float* __restrict__ b_in) {
    int i = blockIdx.x;        // 0..255
    int c = threadIdx.x;       // 0..127
    float w = w_in[i*CH + c];
    g_winf[i*CH + c] = w * g_scale[c];
    float t = w * g_shift[c];
    __shared__ float red[128];
    red[c] = t;
    __syncthreads();
    for (int o = 64; o > 0; o >>= 1) {
        if (c < o) red[c] += red[c+o];
        __syncthreads();
    }
    if (c == 0) g_binf[i] = b_in[i] + red[0];
    if (blockIdx.x == 0 && c < 4) g_bar[c] = 0u;   // graph-replay-safe barrier reset
}

// ---------------- tiled fp32 GEMM, 128x64x16, 256 threads ----------------
// MODE 0: A = x (col-major per (b): A[row,c] = x[b*CH*SEQ + c*SEQ + l]),
//         B = g_winf, out = g_inp, epilogue bias + tanhshrink
// MODE 1: A = g_inp row-major, B = Bext(w_ih), out = g_xgate, bias1+bias2
// MODE 2: A = g_outs row-major, B = Bext(w_out), out = Oext transposed to (B,OC,H,W)
template<int MODE, int N, int K>
__global__ void __launch_bounds__(256)
gemm_k(const float* __restrict__ Aext,
       const float* __restrict__ Bext,
       const float* __restrict__ bias1,
       const float* __restrict__ bias2,
       float* __restrict__ Oext) {
    __shared__ float As[16*132];   // [k][m], stride 132 (16B-aligned, conflict-light)
    __shared__ float Bs[16*68];    // [k][n], stride 68

    const int tid = threadIdx.x;
    const int mBase = blockIdx.x * 128;
    const int nBase = blockIdx.y * 64;

    const float* A  = (MODE == 1) ? g_inp : (MODE == 2 ? g_outs : Aext);
    const float* Bw = (MODE == 0) ? g_winf : Bext;

    float acc[8][4];
#pragma unroll
    for (int i = 0; i < 8; ++i)
#pragma unroll
        for (int j = 0; j < 4; ++j) acc[i][j] = 0.f;

    const int tr = tid & 15;   // row group
    const int tc = tid >> 4;   // col group

    for (int k0 = 0; k0 < K; k0 += 16) {
        // ---- load A tile ----
        if (MODE == 0) {
            int c  = tid >> 4;            // 0..15 (k within tile)
            int m4 = (tid & 15) * 4;      // 0..60
            int b  = mBase >> 10;
            int lb = mBase & 1023;
            const float* src = Aext + b*(CH*SEQ) + (k0 + c)*SEQ + lb;
            *(float4*)&As[c*132 + m4]      = *(const float4*)&src[m4];
            *(float4*)&As[c*132 + m4 + 64] = *(const float4*)&src[m4 + 64];
        } else {
            int r  = tid >> 2;            // 0..63
            int kq = (tid & 3) * 4;
            const float* s0 = A + (size_t)(mBase + r)      * K + k0 + kq;
            const float* s1 = A + (size_t)(mBase + r + 64) * K + k0 + kq;
            float4 v0 = *(const float4*)s0;
            float4 v1 = *(const float4*)s1;
            As[(kq+0)*132 + r] = v0.x; As[(kq+1)*132 + r] = v0.y;
            As[(kq+2)*132 + r] = v0.z; As[(kq+3)*132 + r] = v0.w;
            As[(kq+0)*132 + r + 64] = v1.x; As[(kq+1)*132 + r + 64] = v1.y;
            As[(kq+2)*132 + r + 64] = v1.z; As[(kq+3)*132 + r + 64] = v1.w;
        }
        // ---- load B tile (weights are N x K row-major) ----
        {
            int n  = tid >> 2;            // 0..63
            int kq = (tid & 3) * 4;
            float4 v = *(const float4*)&Bw[(size_t)(nBase + n) * K + k0 + kq];
            Bs[(kq+0)*68 + n] = v.x; Bs[(kq+1)*68 + n] = v.y;
            Bs[(kq+2)*68 + n] = v.z; Bs[(kq+3)*68 + n] = v.w;
        }
        __syncthreads();

#pragma unroll
        for (int k = 0; k < 16; ++k) {
            float4 a0 = *(const float4*)&As[k*132 + tr*4];
            float4 a1 = *(const float4*)&As[k*132 + tr*4 + 64];
            float4 b0 = *(const float4*)&Bs[k*68 + tc*4];
            float av[8] = {a0.x,a0.y,a0.z,a0.w,a1.x,a1.y,a1.z,a1.w};
            float bv[4] = {b0.x,b0.y,b0.z,b0.w};
#pragma unroll
            for (int i = 0; i < 8; ++i)
#pragma unroll
                for (int j = 0; j < 4; ++j)
                    acc[i][j] = fmaf(av[i], bv[j], acc[i][j]);
        }
        __syncthreads();
    }

    // ---- epilogue ----
#pragma unroll
    for (int i = 0; i < 8; ++i) {
        int row = mBase + ((i < 4) ? (tr*4 + i) : (64 + tr*4 + (i-4)));
#pragma unroll
        for (int j = 0; j < 4; ++j) {
            int col = nBase + tc*4 + j;
            float v = acc[i][j];
            if (MODE == 0) {
                v += g_binf[col];
                v = v - tanhf(v);                       // tanhshrink
                g_inp[(size_t)row*N + col] = v;
            } else if (MODE == 1) {
                v += bias1[col] + bias2[col];
                g_xgate[(size_t)row*N + col] = v;
            } else {
                v += bias1[col];
                int b = row >> 10, l = row & 1023;
                Oext[(size_t)b*(OCC*SEQ) + (size_t)col*SEQ + l] = v;
            }
        }
    }
}

// ---------------- persistent RNN kernel ----------------------------------
// 128 blocks = 4 batch-groups (8 batches) x 32 hidden-groups (16 j's).
// Barriers are per batch-group (32 participants) with a monotonic counter.
#define WPAD 516   // padded row stride (floats) for conflict-free f4 LDS
__global__ void __launch_bounds__(256, 1)
rnn_k(const float* __restrict__ w_hh) {
    const int jg = blockIdx.x & 31;
    const int bg = blockIdx.x >> 5;
    const int jbase = jg * 16;
    const int bbase = bg * 8;
    const int tid = threadIdx.x;

    extern __shared__ float dsm[];
    float* w_s = dsm;                   // 16 slots x WPAD
    float* h_s = dsm + 16*WPAD;         // 8 rows x WPAD
    float* part = h_s;                  // aliased after sync (1024 floats)

    // load w_hh rows, permuted so 4-row group loads are conflict-free:
    // slot(j) = (j&3)*4 + (j>>2); read pattern uses rows {jj,4+jj,8+jj,12+jj}
    for (int idx = tid; idx < 16*128; idx += 256) {
        int j  = idx >> 7;
        int k4 = (idx & 127) * 4;
        int slot = ((j & 3) << 2) | (j >> 2);
        *(float4*)&w_s[slot*WPAD + k4] =
            *(const float4*)&w_hh[(size_t)(jbase + j)*RHH + k4];
    }

    const int warp = tid >> 5, lane = tid & 31;
    const int bl = lane >> 2, jq = lane & 3;   // lane = 8 batches x 4 j-quads
    const float* hrow = h_s + bl*WPAD + warp*64;

    int pb = 0;
    unsigned bartarget = 32u;
    for (int l = 0; l < SEQ; ++l) {
        // stage h (prev step) into smem; l==0 uses h0 = 0
        if (l == 0) {
            float4 z = make_float4(0.f,0.f,0.f,0.f);
            for (int idx = tid; idx < 8*128; idx += 256) {
                int b = idx >> 7; int k4 = (idx & 127)*4;
                *(float4*)&h_s[b*WPAD + k4] = z;
            }
        } else {
            const float* hp = g_h[pb];
            for (int idx = tid; idx < 8*128; idx += 256) {
                int b = idx >> 7; int k4 = (idx & 127)*4;
                *(float4*)&h_s[b*WPAD + k4] =
                    *(const float4*)&hp[(bbase + b)*RHH + k4];
            }
        }
        __syncthreads();

        // warp handles k-slice [warp*64, warp*64+64); lane: 1 batch x 4 j's
        float accv[4] = {0.f, 0.f, 0.f, 0.f};
#pragma unroll
        for (int k4 = 0; k4 < 64; k4 += 4) {
            float4 hv = *(const float4*)&hrow[k4];
#pragma unroll
            for (int jj = 0; jj < 4; ++jj) {
                // row j = jq*4+jj lives at slot jj*4+jq  (conflict-free)
                const float4 wv =
                    *(const float4*)&w_s[(jj*4 + jq)*WPAD + warp*64 + k4];
                accv[jj] = fmaf(hv.x, wv.x, accv[jj]);
                accv[jj] = fmaf(hv.y, wv.y, accv[jj]);
                accv[jj] = fmaf(hv.z, wv.z, accv[jj]);
                accv[jj] = fmaf(hv.w, wv.w, accv[jj]);
            }
        }
        __syncthreads();   // done reading h_s (part aliases it)

#pragma unroll
        for (int jj = 0; jj < 4; ++jj)
            part[warp*128 + bl*16 + jq*4 + jj] = accv[jj];
        __syncthreads();

        if (tid < 128) {
            int b = tid >> 4, j = tid & 15;
            float s = 0.f;
#pragma unroll
            for (int w = 0; w < 8; ++w) s += part[w*128 + tid];
            int gb = bbase + b;
            int rowl = (gb << 10) | l;
            s += g_xgate[(size_t)rowl*RHH + jbase + j];
            float hn = tanhf(s);
            g_h[pb ^ 1][gb*RHH + jbase + j] = hn;
            g_outs[(size_t)rowl*RHH + jbase + j] = hn;
        }
        __syncthreads();

        if (l < SEQ - 1) {
            if (tid == 0) {
                __threadfence();
                unsigned v = atomicAdd(&g_bar[bg], 1u) + 1u;
                if (v < bartarget) {
                    volatile unsigned* vp = &g_bar[bg];
                    while (*vp < bartarget) { }
                }
                __threadfence();
            }
            bartarget += 32u;
            __syncthreads();
        }
        pb ^= 1;
    }
}

// ---------------- launch ---------------------------------------------------
extern "C" void kernel_launch(void* const* d_in, const int* in_sizes, int n_in,
                              void* d_out, int out_size) {
    const float* x     = (const float*)d_in[0];
    const float* gamma = (const float*)d_in[1];
    const float* beta  = (const float*)d_in[2];
    const float* w_in  = (const float*)d_in[3];
    const float* b_in  = (const float*)d_in[4];
    const float* w_ih  = (const float*)d_in[5];
    const float* b_ih  = (const float*)d_in[6];
    const float* w_hh  = (const float*)d_in[7];
    const float* b_hh  = (const float*)d_in[8];
    const float* w_out = (const float*)d_in[9];
    const float* b_out = (const float*)d_in[10];
    float* out = (float*)d_out;

    const int rnn_smem = (16 + 8) * WPAD * 4;   // 49536 bytes
    cudaFuncSetAttribute(rnn_k, cudaFuncAttributeMaxDynamicSharedMemorySize,
                         rnn_smem);

    bn_stats_k<<<CH, 256>>>(x, gamma, beta);
    fold_k<<<RINN, 128>>>(w_in, b_in);

    dim3 g1(MTOT/128, RINN/64);   // (256, 4)
    gemm_k<0, RINN, CH><<<g1, 256>>>(x, nullptr, nullptr, nullptr, nullptr);

    dim3 g2(MTOT/128, RHH/64);    // (256, 8)
    gemm_k<1, RHH, RINN><<<g2, 256>>>(nullptr, w_ih, b_ih, b_hh, nullptr);

    rnn_k<<<128, 256, rnn_smem>>>(w_hh);

    dim3 g4(MTOT/128, OCC/64);    // (256, 2)
    gemm_k<2, OCC, RHH><<<g4, 256>>>(nullptr, w_out, b_out, nullptr, out);
}

// round 4
// speedup vs baseline: 1.4815x; 1.4815x over previous
#include <cuda_runtime.h>
#include <math.h>
#include <stdint.h>

#define BATCH 32
#define CH    128
#define SEQ   1024
#define RINN  256
#define RHH   512
#define OCC   128
#define MTOT  (BATCH*SEQ)   // 32768

// ---------------- device scratch (no allocations allowed) ----------------
__device__ float g_scale[CH];
__device__ float g_shift[CH];
__device__ float g_winf[RINN*CH];
__device__ float g_binf[RINN];
__device__ float g_inp[MTOT*RINN];            // (B*L, 256)
__device__ float g_xgate[MTOT*RHH];           // (B*L, 512)
__device__ float g_outs[MTOT*RHH];            // (B*L, 512)

// ---------------- BN statistics -> scale/shift --------------------------
__global__ void bn_stats_k(const float* __restrict__ x,
                           const float* __restrict__ gamma,
                           const float* __restrict__ beta) {
    int c = blockIdx.x;
    int tid = threadIdx.x;
    float s = 0.f, s2 = 0.f;
    for (int i = tid; i < BATCH*SEQ; i += 256) {
        int b = i >> 10, p = i & 1023;
        float v = x[(((b*CH + c) << 10) + p)];
        s += v; s2 += v*v;
    }
    __shared__ float sh0[256], sh1[256];
    sh0[tid] = s; sh1[tid] = s2;
    __syncthreads();
    for (int o = 128; o > 0; o >>= 1) {
        if (tid < o) { sh0[tid] += sh0[tid+o]; sh1[tid] += sh1[tid+o]; }
        __syncthreads();
    }
    if (tid == 0) {
        const float inv = 1.0f / (float)(BATCH*SEQ);
        float mean = sh0[0] * inv;
        float var  = sh1[0] * inv - mean*mean;
        float sc = gamma[c] * rsqrtf(var + 1e-5f);
        g_scale[c] = sc;
        g_shift[c] = beta[c] - mean * sc;
    }
}

// ------------- fold BN into w_in / b_in ---------------------------------
__global__ void fold_k(const float* __restrict__ w_in,
                       const float* __restrict__ b_in) {
    int i = blockIdx.x;        // 0..255
    int c = threadIdx.x;       // 0..127
    float w = w_in[i*CH + c];
    g_winf[i*CH + c] = w * g_scale[c];
    float t = w * g_shift[c];
    __shared__ float red[128];
    red[c] = t;
    __syncthreads();
    for (int o = 64; o > 0; o >>= 1) {
        if (c < o) red[c] += red[c+o];
        __syncthreads();
    }
    if (c == 0) g_binf[i] = b_in[i] + red[0];
}

// ---------------- tiled fp32 GEMM, 128x64x16, 256 threads ----------------
template<int MODE, int N, int K>
__global__ void __launch_bounds__(256)
gemm_k(const float* __restrict__ Aext,
       const float* __restrict__ Bext,
       const float* __restrict__ bias1,
       const float* __restrict__ bias2,
       float* __restrict__ Oext) {
    __shared__ float As[16*132];
    __shared__ float Bs[16*68];

    const int tid = threadIdx.x;
    const int mBase = blockIdx.x * 128;
    const int nBase = blockIdx.y * 64;

    const float* A  = (MODE == 1) ? g_inp : (MODE == 2 ? g_outs : Aext);
    const float* Bw = (MODE == 0) ? g_winf : Bext;

    float acc[8][4];
#pragma unroll
    for (int i = 0; i < 8; ++i)
#pragma unroll
        for (int j = 0; j < 4; ++j) acc[i][j] = 0.f;

    const int tr = tid & 15;
    const int tc = tid >> 4;

    for (int k0 = 0; k0 < K; k0 += 16) {
        if (MODE == 0) {
            int c  = tid >> 4;
            int m4 = (tid & 15) * 4;
            int b  = mBase >> 10;
            int lb = mBase & 1023;
            const float* src = Aext + b*(CH*SEQ) + (k0 + c)*SEQ + lb;
            *(float4*)&As[c*132 + m4]      = *(const float4*)&src[m4];
            *(float4*)&As[c*132 + m4 + 64] = *(const float4*)&src[m4 + 64];
        } else {
            int rr = tid >> 2;
            int kq = (tid & 3) * 4;
            const float* s0 = A + (size_t)(mBase + rr)      * K + k0 + kq;
            const float* s1 = A + (size_t)(mBase + rr + 64) * K + k0 + kq;
            float4 v0 = *(const float4*)s0;
            float4 v1 = *(const float4*)s1;
            As[(kq+0)*132 + rr] = v0.x; As[(kq+1)*132 + rr] = v0.y;
            As[(kq+2)*132 + rr] = v0.z; As[(kq+3)*132 + rr] = v0.w;
            As[(kq+0)*132 + rr + 64] = v1.x; As[(kq+1)*132 + rr + 64] = v1.y;
            As[(kq+2)*132 + rr + 64] = v1.z; As[(kq+3)*132 + rr + 64] = v1.w;
        }
        {
            int n  = tid >> 2;
            int kq = (tid & 3) * 4;
            float4 v = *(const float4*)&Bw[(size_t)(nBase + n) * K + k0 + kq];
            Bs[(kq+0)*68 + n] = v.x; Bs[(kq+1)*68 + n] = v.y;
            Bs[(kq+2)*68 + n] = v.z; Bs[(kq+3)*68 + n] = v.w;
        }
        __syncthreads();

#pragma unroll
        for (int k = 0; k < 16; ++k) {
            float4 a0 = *(const float4*)&As[k*132 + tr*4];
            float4 a1 = *(const float4*)&As[k*132 + tr*4 + 64];
            float4 b0 = *(const float4*)&Bs[k*68 + tc*4];
            float av[8] = {a0.x,a0.y,a0.z,a0.w,a1.x,a1.y,a1.z,a1.w};
            float bv[4] = {b0.x,b0.y,b0.z,b0.w};
#pragma unroll
            for (int i = 0; i < 8; ++i)
#pragma unroll
                for (int j = 0; j < 4; ++j)
                    acc[i][j] = fmaf(av[i], bv[j], acc[i][j]);
        }
        __syncthreads();
    }

#pragma unroll
    for (int i = 0; i < 8; ++i) {
        int row = mBase + ((i < 4) ? (tr*4 + i) : (64 + tr*4 + (i-4)));
#pragma unroll
        for (int j = 0; j < 4; ++j) {
            int col = nBase + tc*4 + j;
            float v = acc[i][j];
            if (MODE == 0) {
                v += g_binf[col];
                v = v - tanhf(v);
                g_inp[(size_t)row*N + col] = v;
            } else if (MODE == 1) {
                v += bias1[col] + bias2[col];
                g_xgate[(size_t)row*N + col] = v;
            } else {
                v += bias1[col];
                int b = row >> 10, l = row & 1023;
                Oext[(size_t)b*(OCC*SEQ) + (size_t)col*SEQ + l] = v;
            }
        }
    }
}

// ---------------- packed fp32x2 helpers ----------------------------------
typedef unsigned long long ull;

__device__ __forceinline__ ull ffma2(ull a, ull b, ull c) {
    ull d; asm("fma.rn.f32x2 %0, %1, %2, %3;" : "=l"(d) : "l"(a), "l"(b), "l"(c)); return d;
}
__device__ __forceinline__ ull addf2(ull a, ull b) {
    ull d; asm("add.rn.f32x2 %0, %1, %2;" : "=l"(d) : "l"(a), "l"(b)); return d;
}
__device__ __forceinline__ ull pack2(float x, float y) {
    ull d; asm("mov.b64 %0, {%1, %2};" : "=l"(d) : "f"(x), "f"(y)); return d;
}
__device__ __forceinline__ ull dup2(float x) {
    ull d; asm("mov.b64 %0, {%1, %1};" : "=l"(d) : "f"(x)); return d;
}
__device__ __forceinline__ void unpack2(ull v, float& x, float& y) {
    asm("mov.b64 {%0, %1}, %2;" : "=f"(x), "=f"(y) : "l"(v));
}

// ---------------- clustered persistent RNN -------------------------------
// 16 clusters x 8 CTAs. Cluster cl handles batches {2cl, 2cl+1}.
// CTA rank r owns hidden units j in [r*64, r*64+64).
// Weights (64 x 512) live in registers (packed j-pairs, f32x2).
// h exchanged via DSMEM (st.shared::cluster), 1 cluster barrier per step.
// h smem layout per batch: 16 groups of 32 floats, stride 36 (bank spread).
#define HSTRIDE 576   // 16 * 36

__global__ void __launch_bounds__(256,1) __cluster_dims__(8,1,1)
rnn_k(const float* __restrict__ w_hh) {
    __shared__ __align__(16) float h_s[2][2][HSTRIDE];

    const int tid  = threadIdx.x;
    const int warp = tid >> 5, lane = tid & 31;
    const int jq   = (warp << 1) | (lane & 1);   // 0..15: which quad of 4 j's
    const int kg   = lane >> 1;                  // 0..15: which 32-wide k slice
    uint32_t r; asm("mov.u32 %0, %%cluster_ctarank;" : "=r"(r));
    const int cl  = blockIdx.x >> 3;
    const int b0g = cl*2, b1g = cl*2 + 1;
    const int jcol  = (int)r*64 + jq*4;          // first of this thread's 4 global j
    const int kbase = kg*32;

    // ---- load w_hh slice into registers, packed per j-pair (lo=j0, hi=j1)
    ull w2[2][32];
#pragma unroll
    for (int jp = 0; jp < 2; ++jp) {
        const float* r0 = w_hh + (size_t)(jcol + jp*2) * RHH + kbase;
        const float* r1 = r0 + RHH;
#pragma unroll
        for (int q = 0; q < 8; ++q) {
            float4 a = *(const float4*)(r0 + q*4);
            float4 b = *(const float4*)(r1 + q*4);
            w2[jp][q*4+0] = pack2(a.x, b.x);
            w2[jp][q*4+1] = pack2(a.y, b.y);
            w2[jp][q*4+2] = pack2(a.z, b.z);
            w2[jp][q*4+3] = pack2(a.w, b.w);
        }
    }

    // ---- zero h buffer 0 (both batches)
    {
        float* z = &h_s[0][0][0];
        for (int i = tid; i < 2*HSTRIDE; i += 256) z[i] = 0.f;
    }
    __syncthreads();
    asm volatile("barrier.cluster.arrive.aligned;" ::: "memory");
    asm volatile("barrier.cluster.wait.aligned;" ::: "memory");

    // peer SMEM base for DSMEM h broadcast (lane's target rank = kg, kg<8)
    uint32_t hbase = (uint32_t)__cvta_generic_to_shared(&h_s[0][0][0]);
    uint32_t peerbase = 0;
    if (kg < 8) {
        asm("mapa.shared::cluster.u32 %0, %1, %2;"
            : "=r"(peerbase) : "r"(hbase), "r"((uint32_t)kg));
    }

    // write position of this thread's 4 j's inside an h buffer
    const int gidx = (int)r*2 + (jq >> 3);       // 32-group index
    const int woff = (jq & 7) * 4;               // offset within group
    const uint32_t wbyte = (uint32_t)((gidx*36 + woff) * 4);

    // prefetch xgate for l = 0
    float4 xg0 = *(const float4*)&g_xgate[(size_t)(b0g << 10)*RHH + jcol];
    float4 xg1 = *(const float4*)&g_xgate[(size_t)(b1g << 10)*RHH + jcol];

    for (int l = 0; l < SEQ; ++l) {
        const int p = l & 1;
        const float* hb0 = &h_s[p][0][kg*36];
        const float* hb1 = &h_s[p][1][kg*36];

        ull a00 = 0ull, a01 = 0ull, a10 = 0ull, a11 = 0ull;  // [batch][jpair]
#pragma unroll
        for (int q = 0; q < 8; ++q) {
            float4 h0 = *(const float4*)(hb0 + q*4);
            float4 h1 = *(const float4*)(hb1 + q*4);
            ull hp;
            hp = dup2(h0.x); a00 = ffma2(hp, w2[0][q*4+0], a00); a01 = ffma2(hp, w2[1][q*4+0], a01);
            hp = dup2(h1.x); a10 = ffma2(hp, w2[0][q*4+0], a10); a11 = ffma2(hp, w2[1][q*4+0], a11);
            hp = dup2(h0.y); a00 = ffma2(hp, w2[0][q*4+1], a00); a01 = ffma2(hp, w2[1][q*4+1], a01);
            hp = dup2(h1.y); a10 = ffma2(hp, w2[0][q*4+1], a10); a11 = ffma2(hp, w2[1][q*4+1], a11);
            hp = dup2(h0.z); a00 = ffma2(hp, w2[0][q*4+2], a00); a01 = ffma2(hp, w2[1][q*4+2], a01);
            hp = dup2(h1.z); a10 = ffma2(hp, w2[0][q*4+2], a10); a11 = ffma2(hp, w2[1][q*4+2], a11);
            hp = dup2(h0.w); a00 = ffma2(hp, w2[0][q*4+3], a00); a01 = ffma2(hp, w2[1][q*4+3], a01);
            hp = dup2(h1.w); a10 = ffma2(hp, w2[0][q*4+3], a10); a11 = ffma2(hp, w2[1][q*4+3], a11);
        }

        // butterfly reduce over kg (lane bits 1..4); jq bit (lane bit 0) untouched
#pragma unroll
        for (int m = 2; m <= 16; m <<= 1) {
            a00 = addf2(a00, __shfl_xor_sync(0xffffffffu, a00, m));
            a01 = addf2(a01, __shfl_xor_sync(0xffffffffu, a01, m));
            a10 = addf2(a10, __shfl_xor_sync(0xffffffffu, a10, m));
            a11 = addf2(a11, __shfl_xor_sync(0xffffffffu, a11, m));
        }

        float s0, s1;
        unpack2(a00, s0, s1); float h00 = tanhf(s0 + xg0.x), h01 = tanhf(s1 + xg0.y);
        unpack2(a01, s0, s1); float h02 = tanhf(s0 + xg0.z), h03 = tanhf(s1 + xg0.w);
        unpack2(a10, s0, s1); float h10 = tanhf(s0 + xg1.x), h11 = tanhf(s1 + xg1.y);
        unpack2(a11, s0, s1); float h12 = tanhf(s0 + xg1.z), h13 = tanhf(s1 + xg1.w);

        if (kg == 8) {  // one writer lane-pair per jq: persist outputs
            size_t row0 = (size_t)((b0g << 10) | l);
            size_t row1 = (size_t)((b1g << 10) | l);
            *(float4*)&g_outs[row0*RHH + jcol] = make_float4(h00, h01, h02, h03);
            *(float4*)&g_outs[row1*RHH + jcol] = make_float4(h10, h11, h12, h13);
        }

        if (l < SEQ - 1) {
            if (kg < 8) {  // broadcast new h to cluster CTA `kg`
                uint32_t base = peerbase
                              + (uint32_t)(((p ^ 1) * 2) * HSTRIDE * 4) + wbyte;
                ull v;
                v = pack2(h00, h01);
                asm volatile("st.shared::cluster.b64 [%0], %1;" :: "r"(base),                  "l"(v) : "memory");
                v = pack2(h02, h03);
                asm volatile("st.shared::cluster.b64 [%0], %1;" :: "r"(base + 8),              "l"(v) : "memory");
                v = pack2(h10, h11);
                asm volatile("st.shared::cluster.b64 [%0], %1;" :: "r"(base + HSTRIDE*4),      "l"(v) : "memory");
                v = pack2(h12, h13);
                asm volatile("st.shared::cluster.b64 [%0], %1;" :: "r"(base + HSTRIDE*4 + 8),  "l"(v) : "memory");
            }
            asm volatile("barrier.cluster.arrive.aligned;" ::: "memory");
            // prefetch next step's xgate while waiting
            int l1 = l + 1;
            xg0 = *(const float4*)&g_xgate[(size_t)((b0g << 10) | l1)*RHH + jcol];
            xg1 = *(const float4*)&g_xgate[(size_t)((b1g << 10) | l1)*RHH + jcol];
            asm volatile("barrier.cluster.wait.aligned;" ::: "memory");
        }
    }
}

// ---------------- launch ---------------------------------------------------
extern "C" void kernel_launch(void* const* d_in, const int* in_sizes, int n_in,
                              void* d_out, int out_size) {
    const float* x     = (const float*)d_in[0];
    const float* gamma = (const float*)d_in[1];
    const float* beta  = (const float*)d_in[2];
    const float* w_in  = (const float*)d_in[3];
    const float* b_in  = (const float*)d_in[4];
    const float* w_ih  = (const float*)d_in[5];
    const float* b_ih  = (const float*)d_in[6];
    const float* w_hh  = (const float*)d_in[7];
    const float* b_hh  = (const float*)d_in[8];
    const float* w_out = (const float*)d_in[9];
    const float* b_out = (const float*)d_in[10];
    float* out = (float*)d_out;

    bn_stats_k<<<CH, 256>>>(x, gamma, beta);
    fold_k<<<RINN, 128>>>(w_in, b_in);

    dim3 g1(MTOT/128, RINN/64);
    gemm_k<0, RINN, CH><<<g1, 256>>>(x, nullptr, nullptr, nullptr, nullptr);

    dim3 g2(MTOT/128, RHH/64);
    gemm_k<1, RHH, RINN><<<g2, 256>>>(nullptr, w_ih, b_ih, b_hh, nullptr);

    rnn_k<<<128, 256>>>(w_hh);

    dim3 g4(MTOT/128, OCC/64);
    gemm_k<2, OCC, RHH><<<g4, 256>>>(nullptr, w_out, b_out, nullptr, out);
}